// round 2
// baseline (speedup 1.0000x reference)
#include <cuda_runtime.h>
#include <math.h>

#define CC   256
#define CQ   32
#define NPIX 4096
#define EPSB 1e-5f

typedef unsigned long long u64;

// ---- packed f32x2 helpers (Blackwell FFMA2: 2 fp32 FMAs per fma-pipe issue) ----
__device__ __forceinline__ u64 pack2(float lo, float hi) {
    u64 r; asm("mov.b64 %0, {%1, %2};" : "=l"(r) : "f"(lo), "f"(hi)); return r;
}
__device__ __forceinline__ void fma2(u64& d, u64 a, u64 b) {
    asm("fma.rn.f32x2 %0, %1, %2, %0;" : "+l"(d) : "l"(a), "l"(b));
}
__device__ __forceinline__ float2 unpack2(u64 v) {
    float2 f; asm("mov.b64 {%0, %1}, %2;" : "=f"(f.x), "=f"(f.y) : "l"(v)); return f;
}
__device__ __forceinline__ u64 lds_pair(const float* p) {   // 8B-aligned smem pair
    return *reinterpret_cast<const u64*>(p);
}

// ---------------- scratch (static device arrays; no allocation) ----------------
__device__ float g_xf1[CC * NPIX];
__device__ float g_xf2[CC * NPIX];
__device__ float g_qb[CQ * NPIX];
__device__ float g_kb[CQ * NPIX];
__device__ float g_vb[CC * NPIX];
__device__ float g_attn[(size_t)NPIX * NPIX];   // 64 MB

// ---------------------------------------------------------------------------
// Fused dual conv3x3 + eval-BN + magnitude.
// GEMM view: M=256, N=4096, K=9*256, k = tap*256 + ci.
// grid (64, 4), block 256.
// ---------------------------------------------------------------------------
__global__ void sobel_kernel(const float* __restrict__ x,
                             const float* __restrict__ wx,
                             const float* __restrict__ wy,
                             const float* __restrict__ bnx,
                             const float* __restrict__ bny,
                             float* __restrict__ out)
{
    __shared__ float Ax[64][18];
    __shared__ float Ay[64][18];
    __shared__ float Bs[16][64];

    const int tid = threadIdx.x;
    const int tx = tid & 15, ty = tid >> 4;
    const int m0 = blockIdx.y * 64;
    const int n0 = blockIdx.x * 64;
    const int row_y = blockIdx.x;

    u64 accx[4][2] = {};
    u64 accy[4][2] = {};

    for (int kt = 0; kt < 9 * 256; kt += 16) {
        const int tap = kt >> 8;
        const int dy = tap / 3 - 1;
        const int dx = tap % 3 - 1;

        #pragma unroll
        for (int r = 0; r < 4; r++) {
            int idx = tid + r * 256;
            int am = idx >> 4, ak = idx & 15;
            int k  = kt + ak;
            int ci = k & 255;
            int tp = k >> 8;
            int widx = (m0 + am) * 2304 + ci * 9 + tp;
            Ax[am][ak] = wx[widx];
            Ay[am][ak] = wy[widx];
        }
        {
            const int yy = row_y + dy;
            const bool yok = (yy >= 0) && (yy < 64);
            #pragma unroll
            for (int r = 0; r < 4; r++) {
                int idx = tid + r * 256;
                int bk = idx >> 6, bn = idx & 63;
                int ci = (kt + bk) & 255;
                int xx = bn + dx;
                float v = 0.f;
                if (yok && xx >= 0 && xx < 64)
                    v = x[ci * NPIX + yy * 64 + xx];
                Bs[bk][bn] = v;
            }
        }
        __syncthreads();

        #pragma unroll
        for (int kk = 0; kk < 16; kk++) {
            u64 b0 = lds_pair(&Bs[kk][tx * 4]);
            u64 b1 = lds_pair(&Bs[kk][tx * 4 + 2]);
            #pragma unroll
            for (int i = 0; i < 4; i++) {
                float axv = Ax[ty*4+i][kk];
                float ayv = Ay[ty*4+i][kk];
                u64 aax = pack2(axv, axv);
                u64 aay = pack2(ayv, ayv);
                fma2(accx[i][0], aax, b0);
                fma2(accx[i][1], aax, b1);
                fma2(accy[i][0], aay, b0);
                fma2(accy[i][1], aay, b1);
            }
        }
        __syncthreads();
    }

    #pragma unroll
    for (int i = 0; i < 4; i++) {
        const int m = m0 + ty * 4 + i;
        const float invx = bnx[m] * rsqrtf(bnx[768 + m] + EPSB);
        const float bx_  = bnx[256 + m];
        const float mx_  = bnx[512 + m];
        const float invy = bny[m] * rsqrtf(bny[768 + m] + EPSB);
        const float by_  = bny[256 + m];
        const float my_  = bny[512 + m];
        float ax_[4], ay_[4];
        float2 t;
        t = unpack2(accx[i][0]); ax_[0] = t.x; ax_[1] = t.y;
        t = unpack2(accx[i][1]); ax_[2] = t.x; ax_[3] = t.y;
        t = unpack2(accy[i][0]); ay_[0] = t.x; ay_[1] = t.y;
        t = unpack2(accy[i][1]); ay_[2] = t.x; ay_[3] = t.y;
        #pragma unroll
        for (int j = 0; j < 4; j++) {
            const int n = n0 + tx * 4 + j;
            float a = (ax_[j] - mx_) * invx + bx_;
            float b = (ay_[j] - my_) * invy + by_;
            out[m * NPIX + n] = sqrtf(a * a + b * b);
        }
    }
}

// ---------------------------------------------------------------------------
// out[M][4096] = A[M][256] * B[256][4096] + bias[M]   (M = 32 or 256)
// grid (64, ceil(M/64)), block 256.
// ---------------------------------------------------------------------------
__global__ void gemm_bias_kernel(const float* __restrict__ A,
                                 const float* __restrict__ B,
                                 const float* __restrict__ bias,
                                 float* __restrict__ out,
                                 int M)
{
    __shared__ float As[64][18];
    __shared__ float Bs[16][64];
    const int tid = threadIdx.x;
    const int tx = tid & 15, ty = tid >> 4;
    const int m0 = blockIdx.y * 64, n0 = blockIdx.x * 64;
    u64 acc[4][2] = {};

    for (int kt = 0; kt < 256; kt += 16) {
        #pragma unroll
        for (int r = 0; r < 4; r++) {
            int idx = tid + r * 256;
            int am = idx >> 4, ak = idx & 15;
            int m = m0 + am;
            As[am][ak] = (m < M) ? A[m * 256 + kt + ak] : 0.f;
        }
        #pragma unroll
        for (int r = 0; r < 4; r++) {
            int idx = tid + r * 256;
            int bk = idx >> 6, bn = idx & 63;
            Bs[bk][bn] = B[(kt + bk) * NPIX + n0 + bn];
        }
        __syncthreads();
        #pragma unroll
        for (int kk = 0; kk < 16; kk++) {
            u64 b0 = lds_pair(&Bs[kk][tx * 4]);
            u64 b1 = lds_pair(&Bs[kk][tx * 4 + 2]);
            #pragma unroll
            for (int i = 0; i < 4; i++) {
                float av = As[ty*4+i][kk];
                u64 aa = pack2(av, av);
                fma2(acc[i][0], aa, b0);
                fma2(acc[i][1], aa, b1);
            }
        }
        __syncthreads();
    }

    #pragma unroll
    for (int i = 0; i < 4; i++) {
        int m = m0 + ty * 4 + i;
        if (m < M) {
            float bb = bias[m];
            float2 t0 = unpack2(acc[i][0]);
            float2 t1 = unpack2(acc[i][1]);
            float* o = out + m * NPIX + n0 + tx * 4;
            o[0] = t0.x + bb;
            o[1] = t0.y + bb;
            o[2] = t1.x + bb;
            o[3] = t1.y + bb;
        }
    }
}

// ---------------------------------------------------------------------------
// energy[m][n] = sum_{c<32} q[c][m] * k[c][n]
// grid (64, 64), block 256.
// ---------------------------------------------------------------------------
__global__ void energy_kernel(const float* __restrict__ q,
                              const float* __restrict__ k,
                              float* __restrict__ e)
{
    __shared__ float As[32][64];
    __shared__ float Bs[32][64];
    const int tid = threadIdx.x;
    const int tx = tid & 15, ty = tid >> 4;
    const int m0 = blockIdx.y * 64, n0 = blockIdx.x * 64;

    #pragma unroll
    for (int r = 0; r < 8; r++) {
        int idx = tid + r * 256;
        int c = idx >> 6, mm = idx & 63;
        As[c][mm] = q[c * NPIX + m0 + mm];
        Bs[c][mm] = k[c * NPIX + n0 + mm];
    }
    __syncthreads();

    u64 acc[4][2] = {};
    #pragma unroll
    for (int c = 0; c < 32; c++) {
        u64 b0 = lds_pair(&Bs[c][tx * 4]);
        u64 b1 = lds_pair(&Bs[c][tx * 4 + 2]);
        #pragma unroll
        for (int i = 0; i < 4; i++) {
            float av = As[c][ty*4+i];
            u64 aa = pack2(av, av);
            fma2(acc[i][0], aa, b0);
            fma2(acc[i][1], aa, b1);
        }
    }
    #pragma unroll
    for (int i = 0; i < 4; i++) {
        float2 t0 = unpack2(acc[i][0]);
        float2 t1 = unpack2(acc[i][1]);
        float* o = e + (size_t)(m0 + ty*4 + i) * NPIX + n0 + tx*4;
        o[0] = t0.x; o[1] = t0.y; o[2] = t1.x; o[3] = t1.y;
    }
}

// ---------------------------------------------------------------------------
// In-place row softmax over 4096 columns. grid 4096, block 256.
// ---------------------------------------------------------------------------
__global__ void softmax_kernel(float* __restrict__ e)
{
    __shared__ float red[8];
    float4* p = (float4*)(e + (size_t)blockIdx.x * NPIX);
    const int tid = threadIdx.x;
    float4 v[4];
    float mx = -1e30f;
    #pragma unroll
    for (int r = 0; r < 4; r++) {
        v[r] = p[tid + r * 256];
        mx = fmaxf(mx, fmaxf(fmaxf(v[r].x, v[r].y), fmaxf(v[r].z, v[r].w)));
    }
    #pragma unroll
    for (int o = 16; o > 0; o >>= 1)
        mx = fmaxf(mx, __shfl_xor_sync(0xffffffffu, mx, o));
    if ((tid & 31) == 0) red[tid >> 5] = mx;
    __syncthreads();
    mx = red[0];
    #pragma unroll
    for (int w = 1; w < 8; w++) mx = fmaxf(mx, red[w]);
    __syncthreads();

    float s = 0.f;
    #pragma unroll
    for (int r = 0; r < 4; r++) {
        v[r].x = __expf(v[r].x - mx); s += v[r].x;
        v[r].y = __expf(v[r].y - mx); s += v[r].y;
        v[r].z = __expf(v[r].z - mx); s += v[r].z;
        v[r].w = __expf(v[r].w - mx); s += v[r].w;
    }
    #pragma unroll
    for (int o = 16; o > 0; o >>= 1)
        s += __shfl_xor_sync(0xffffffffu, s, o);
    if ((tid & 31) == 0) red[tid >> 5] = s;
    __syncthreads();
    s = 0.f;
    #pragma unroll
    for (int w = 0; w < 8; w++) s += red[w];
    const float inv = 1.f / s;
    #pragma unroll
    for (int r = 0; r < 4; r++) {
        v[r].x *= inv; v[r].y *= inv; v[r].z *= inv; v[r].w *= inv;
        p[tid + r * 256] = v[r];
    }
}

// ---------------------------------------------------------------------------
// out[m][n] = gamma * sum_k v[m][k] * attn[n][k] + xq[m][n]
// M=256, N=4096, K=4096.  grid (64, 4), block 256.
// ---------------------------------------------------------------------------
__global__ void av_kernel(const float* __restrict__ vmat,
                          const float* __restrict__ attn,
                          const float* __restrict__ xq,
                          const float* __restrict__ gamma,
                          float* __restrict__ out)
{
    __shared__ float As[64][33];
    __shared__ float Bs[32][66];
    const int tid = threadIdx.x;
    const int tx = tid & 15, ty = tid >> 4;
    const int m0 = blockIdx.y * 64, n0 = blockIdx.x * 64;
    u64 acc[4][2] = {};

    for (int kt = 0; kt < NPIX; kt += 32) {
        #pragma unroll
        for (int r = 0; r < 8; r++) {
            int idx = tid + r * 256;
            int am = idx >> 5, ak = idx & 31;
            As[am][ak] = vmat[(m0 + am) * NPIX + kt + ak];
        }
        #pragma unroll
        for (int r = 0; r < 8; r++) {
            int idx = tid + r * 256;
            int bn = idx >> 5, bk = idx & 31;
            Bs[bk][bn] = attn[(size_t)(n0 + bn) * NPIX + kt + bk];
        }
        __syncthreads();
        #pragma unroll
        for (int kk = 0; kk < 32; kk++) {
            u64 b0 = lds_pair(&Bs[kk][tx * 4]);
            u64 b1 = lds_pair(&Bs[kk][tx * 4 + 2]);
            #pragma unroll
            for (int i = 0; i < 4; i++) {
                float av = As[ty*4+i][kk];
                u64 aa = pack2(av, av);
                fma2(acc[i][0], aa, b0);
                fma2(acc[i][1], aa, b1);
            }
        }
        __syncthreads();
    }

    const float g = gamma[0];
    #pragma unroll
    for (int i = 0; i < 4; i++) {
        const int m = m0 + ty * 4 + i;
        float2 t0 = unpack2(acc[i][0]);
        float2 t1 = unpack2(acc[i][1]);
        const float* xr = xq + m * NPIX + n0 + tx * 4;
        float* o = out + m * NPIX + n0 + tx * 4;
        o[0] = g * t0.x + xr[0];
        o[1] = g * t0.y + xr[1];
        o[2] = g * t1.x + xr[2];
        o[3] = g * t1.y + xr[3];
    }
}

// ---------------------------------------------------------------------------
extern "C" void kernel_launch(void* const* d_in, const int* in_sizes, int n_in,
                              void* d_out, int out_size)
{
    const float* x1    = (const float*)d_in[0];
    const float* x2    = (const float*)d_in[1];
    const float* sx1_w = (const float*)d_in[2];
    const float* sy1_w = (const float*)d_in[3];
    const float* bn1x  = (const float*)d_in[4];
    const float* bn1y  = (const float*)d_in[5];
    const float* sx2_w = (const float*)d_in[6];
    const float* sy2_w = (const float*)d_in[7];
    const float* bn2x  = (const float*)d_in[8];
    const float* bn2y  = (const float*)d_in[9];
    const float* q1_w  = (const float*)d_in[10];
    const float* q1_b  = (const float*)d_in[11];
    const float* k1_w  = (const float*)d_in[12];
    const float* k1_b  = (const float*)d_in[13];
    const float* v1_w  = (const float*)d_in[14];
    const float* v1_b  = (const float*)d_in[15];
    const float* q2_w  = (const float*)d_in[16];
    const float* q2_b  = (const float*)d_in[17];
    const float* k2_w  = (const float*)d_in[18];
    const float* k2_b  = (const float*)d_in[19];
    const float* v2_w  = (const float*)d_in[20];
    const float* v2_b  = (const float*)d_in[21];
    const float* gamma1 = (const float*)d_in[22];
    const float* gamma2 = (const float*)d_in[23];
    float* out = (float*)d_out;

    float *xf1, *xf2, *qb, *kb, *vb, *attn;
    cudaGetSymbolAddress((void**)&xf1, g_xf1);
    cudaGetSymbolAddress((void**)&xf2, g_xf2);
    cudaGetSymbolAddress((void**)&qb,  g_qb);
    cudaGetSymbolAddress((void**)&kb,  g_kb);
    cudaGetSymbolAddress((void**)&vb,  g_vb);
    cudaGetSymbolAddress((void**)&attn, g_attn);

    dim3 blk(256);

    sobel_kernel<<<dim3(64, 4), blk>>>(x1, sx1_w, sy1_w, bn1x, bn1y, xf1);
    sobel_kernel<<<dim3(64, 4), blk>>>(x2, sx2_w, sy2_w, bn2x, bn2y, xf2);

    // ---- attention 1: q from x1, k/v from xf2 -> out1 ----
    gemm_bias_kernel<<<dim3(64, 1), blk>>>(q1_w, x1,  q1_b, qb, CQ);
    gemm_bias_kernel<<<dim3(64, 1), blk>>>(k1_w, xf2, k1_b, kb, CQ);
    gemm_bias_kernel<<<dim3(64, 4), blk>>>(v1_w, xf2, v1_b, vb, CC);
    energy_kernel<<<dim3(64, 64), blk>>>(qb, kb, attn);
    softmax_kernel<<<NPIX, 256>>>(attn);
    av_kernel<<<dim3(64, 4), blk>>>(vb, attn, x1, gamma1, out);

    // ---- attention 2: q from x2, k/v from xf1 -> out2 ----
    gemm_bias_kernel<<<dim3(64, 1), blk>>>(q2_w, x2,  q2_b, qb, CQ);
    gemm_bias_kernel<<<dim3(64, 1), blk>>>(k2_w, xf1, k2_b, kb, CQ);
    gemm_bias_kernel<<<dim3(64, 4), blk>>>(v2_w, xf1, v2_b, vb, CC);
    energy_kernel<<<dim3(64, 64), blk>>>(qb, kb, attn);
    softmax_kernel<<<NPIX, 256>>>(attn);
    av_kernel<<<dim3(64, 4), blk>>>(vb, attn, x2, gamma2, out + CC * NPIX);
}

// round 3
// speedup vs baseline: 1.8938x; 1.8938x over previous
#include <cuda_runtime.h>
#include <math.h>

#define CC   256
#define CQ   32
#define NPIX 4096
#define EPSB 1e-5f
#define KW   2304          // 9*256 conv K

// smem row pads (uint elements) chosen for conflict-free fragment LDS
#define PA 36              // A tiles [m][k], KC=32:  (4m+k) mod 32 injective
#define PB 136             // B tiles [k][n], N=128:  (8k+n) mod 32 injective
#define PT 36              // B-transposed tiles [n][k]: (4n+k) mod 32 injective
#define PQ 68              // q tile [c][m], m-tile 64: (4c+m) mod 32 injective

// ---------------- scratch (static device arrays; no allocation) ----------------
__device__ float g_xf1[CC * NPIX];
__device__ float g_xf2[CC * NPIX];
__device__ float g_qb[CQ * NPIX];
__device__ float g_kb[CQ * NPIX];
__device__ float g_vb[CC * NPIX];
__device__ float g_attn[(size_t)NPIX * NPIX];   // 64 MB
__device__ float g_wx1p[CC * KW];
__device__ float g_wy1p[CC * KW];
__device__ float g_wx2p[CC * KW];
__device__ float g_wy2p[CC * KW];

// ---------------- tf32 mma helpers ----------------
__device__ __forceinline__ unsigned f2tf32(float x) {
    unsigned r; asm("cvt.rna.tf32.f32 %0, %1;" : "=r"(r) : "f"(x)); return r;
}
__device__ __forceinline__ void mma8(float* c, const unsigned* a, const unsigned* b) {
    asm volatile(
        "mma.sync.aligned.m16n8k8.row.col.f32.tf32.tf32.f32 "
        "{%0,%1,%2,%3}, {%4,%5,%6,%7}, {%8,%9}, {%0,%1,%2,%3};"
        : "+f"(c[0]), "+f"(c[1]), "+f"(c[2]), "+f"(c[3])
        : "r"(a[0]), "r"(a[1]), "r"(a[2]), "r"(a[3]), "r"(b[0]), "r"(b[1]));
}

// ---------------------------------------------------------------------------
// Pre-pack conv weights: wpk[m][k] with k = tap*256 + ci  (from w[m][ci][tap])
// ---------------------------------------------------------------------------
__global__ void pack_w(const float* __restrict__ w, float* __restrict__ o)
{
    int t = blockIdx.x * 256 + threadIdx.x;      // 0 .. 256*2304-1
    int m = t / KW, r = t % KW;
    int tp = r >> 8, ci = r & 255;
    o[t] = w[m * KW + ci * 9 + tp];
}

// ---------------------------------------------------------------------------
// Sobel: dual conv3x3 (as GEMM, M=256,N=4096,K=2304) + BN + magnitude.
// block 256 (8 warps 2x4), block tile 64(M) x 128(N), grid (32, 4).
// ---------------------------------------------------------------------------
__global__ void sobel_mma(const float* __restrict__ x,
                          const float* __restrict__ wxp,
                          const float* __restrict__ wyp,
                          const float* __restrict__ bnx,
                          const float* __restrict__ bny,
                          float* __restrict__ out)
{
    __shared__ unsigned Axs[64 * PA];
    __shared__ unsigned Ays[64 * PA];
    __shared__ unsigned Bs [32 * PB];

    const int tid = threadIdx.x;
    const int lane = tid & 31, wid = tid >> 5;
    const int g = lane >> 2, tig = lane & 3;
    const int m_off = (wid >> 2) * 32, n_off = (wid & 3) * 32;
    const int m0 = blockIdx.y * 64, n0 = blockIdx.x * 128;

    float accx[2][4][4] = {};
    float accy[2][4][4] = {};

    for (int kt = 0; kt < KW; kt += 32) {
        // ---- A tiles (packed weights, coalesced) ----
        #pragma unroll
        for (int r = 0; r < 2; r++) {
            int idx = tid + r * 256;
            int m = idx >> 3, c4 = (idx & 7) * 4;
            float4 vx = *(const float4*)&wxp[(m0 + m) * KW + kt + c4];
            float4 vy = *(const float4*)&wyp[(m0 + m) * KW + kt + c4];
            unsigned* ax = &Axs[m * PA + c4];
            unsigned* ay = &Ays[m * PA + c4];
            ax[0] = f2tf32(vx.x); ax[1] = f2tf32(vx.y); ax[2] = f2tf32(vx.z); ax[3] = f2tf32(vx.w);
            ay[0] = f2tf32(vy.x); ay[1] = f2tf32(vy.y); ay[2] = f2tf32(vy.z); ay[3] = f2tf32(vy.w);
        }
        // ---- B tile: shifted image, k = tap*256 + ci (tap constant per chunk) ----
        {
            const int tap = kt >> 8;
            const int dy = tap / 3 - 1, dx = tap % 3 - 1;
            const int cibase = kt & 255;
            #pragma unroll
            for (int r = 0; r < 4; r++) {
                int idx = tid + r * 256;
                int kl = idx >> 5, c4 = (idx & 31) * 4;
                int ci = cibase + kl;
                unsigned v[4];
                #pragma unroll
                for (int j = 0; j < 4; j++) {
                    int pix = n0 + c4 + j;
                    int yy = (pix >> 6) + dy;
                    int xx = (pix & 63) + dx;
                    float f = 0.f;
                    if (yy >= 0 && yy < 64 && xx >= 0 && xx < 64)
                        f = x[ci * NPIX + yy * 64 + xx];
                    v[j] = f2tf32(f);
                }
                *(uint4*)&Bs[kl * PB + c4] = make_uint4(v[0], v[1], v[2], v[3]);
            }
        }
        __syncthreads();

        #pragma unroll
        for (int ks = 0; ks < 4; ks++) {
            const int k0 = ks * 8;
            unsigned ax[2][4], ay[2][4], b[4][2];
            #pragma unroll
            for (int mf = 0; mf < 2; mf++) {
                int mr = m_off + mf * 16 + g;
                ax[mf][0] = Axs[mr * PA + k0 + tig];
                ax[mf][1] = Axs[(mr + 8) * PA + k0 + tig];
                ax[mf][2] = Axs[mr * PA + k0 + tig + 4];
                ax[mf][3] = Axs[(mr + 8) * PA + k0 + tig + 4];
                ay[mf][0] = Ays[mr * PA + k0 + tig];
                ay[mf][1] = Ays[(mr + 8) * PA + k0 + tig];
                ay[mf][2] = Ays[mr * PA + k0 + tig + 4];
                ay[mf][3] = Ays[(mr + 8) * PA + k0 + tig + 4];
            }
            #pragma unroll
            for (int nf = 0; nf < 4; nf++) {
                int nc = n_off + nf * 8 + g;
                b[nf][0] = Bs[(k0 + tig) * PB + nc];
                b[nf][1] = Bs[(k0 + tig + 4) * PB + nc];
            }
            #pragma unroll
            for (int mf = 0; mf < 2; mf++)
                #pragma unroll
                for (int nf = 0; nf < 4; nf++) {
                    mma8(accx[mf][nf], ax[mf], b[nf]);
                    mma8(accy[mf][nf], ay[mf], b[nf]);
                }
        }
        __syncthreads();
    }

    // ---- epilogue: BN + magnitude ----
    #pragma unroll
    for (int mf = 0; mf < 2; mf++) {
        int r0 = m0 + m_off + mf * 16 + g;
        int r1 = r0 + 8;
        float ivx0 = bnx[r0] * rsqrtf(bnx[768 + r0] + EPSB);
        float ivx1 = bnx[r1] * rsqrtf(bnx[768 + r1] + EPSB);
        float bx0 = bnx[256 + r0], bx1 = bnx[256 + r1];
        float mx0 = bnx[512 + r0], mx1 = bnx[512 + r1];
        float ivy0 = bny[r0] * rsqrtf(bny[768 + r0] + EPSB);
        float ivy1 = bny[r1] * rsqrtf(bny[768 + r1] + EPSB);
        float by0 = bny[256 + r0], by1 = bny[256 + r1];
        float my0 = bny[512 + r0], my1 = bny[512 + r1];
        #pragma unroll
        for (int nf = 0; nf < 4; nf++) {
            int col = n0 + n_off + nf * 8 + 2 * tig;
            float gx, gy;
            float2 o0, o1;
            gx = (accx[mf][nf][0] - mx0) * ivx0 + bx0;
            gy = (accy[mf][nf][0] - my0) * ivy0 + by0;
            o0.x = sqrtf(gx * gx + gy * gy);
            gx = (accx[mf][nf][1] - mx0) * ivx0 + bx0;
            gy = (accy[mf][nf][1] - my0) * ivy0 + by0;
            o0.y = sqrtf(gx * gx + gy * gy);
            gx = (accx[mf][nf][2] - mx1) * ivx1 + bx1;
            gy = (accy[mf][nf][2] - my1) * ivy1 + by1;
            o1.x = sqrtf(gx * gx + gy * gy);
            gx = (accx[mf][nf][3] - mx1) * ivx1 + bx1;
            gy = (accy[mf][nf][3] - my1) * ivy1 + by1;
            o1.y = sqrtf(gx * gx + gy * gy);
            *(float2*)&out[r0 * NPIX + col] = o0;
            *(float2*)&out[r1 * NPIX + col] = o1;
        }
    }
}

// ---------------------------------------------------------------------------
// proj: out[M][4096] = W[M][256] * B[256][4096] + bias.  grid (32, ceil(M/64)).
// ---------------------------------------------------------------------------
__global__ void proj_mma(const float* __restrict__ A,
                         const float* __restrict__ B,
                         const float* __restrict__ bias,
                         float* __restrict__ out, int M)
{
    __shared__ unsigned As[64 * PA];
    __shared__ unsigned Bs[32 * PB];

    const int tid = threadIdx.x;
    const int lane = tid & 31, wid = tid >> 5;
    const int g = lane >> 2, tig = lane & 3;
    const int m_off = (wid >> 2) * 32, n_off = (wid & 3) * 32;
    const int m0 = blockIdx.y * 64, n0 = blockIdx.x * 128;

    float acc[2][4][4] = {};

    for (int kt = 0; kt < 256; kt += 32) {
        #pragma unroll
        for (int r = 0; r < 2; r++) {
            int idx = tid + r * 256;
            int m = idx >> 3, c4 = (idx & 7) * 4;
            float4 v = make_float4(0.f, 0.f, 0.f, 0.f);
            if (m0 + m < M) v = *(const float4*)&A[(m0 + m) * 256 + kt + c4];
            unsigned* a = &As[m * PA + c4];
            a[0] = f2tf32(v.x); a[1] = f2tf32(v.y); a[2] = f2tf32(v.z); a[3] = f2tf32(v.w);
        }
        #pragma unroll
        for (int r = 0; r < 4; r++) {
            int idx = tid + r * 256;
            int k = idx >> 5, c4 = (idx & 31) * 4;
            float4 v = *(const float4*)&B[(kt + k) * NPIX + n0 + c4];
            unsigned* bp = &Bs[k * PB + c4];
            bp[0] = f2tf32(v.x); bp[1] = f2tf32(v.y); bp[2] = f2tf32(v.z); bp[3] = f2tf32(v.w);
        }
        __syncthreads();
        #pragma unroll
        for (int ks = 0; ks < 4; ks++) {
            const int k0 = ks * 8;
            unsigned a[2][4], b[4][2];
            #pragma unroll
            for (int mf = 0; mf < 2; mf++) {
                int mr = m_off + mf * 16 + g;
                a[mf][0] = As[mr * PA + k0 + tig];
                a[mf][1] = As[(mr + 8) * PA + k0 + tig];
                a[mf][2] = As[mr * PA + k0 + tig + 4];
                a[mf][3] = As[(mr + 8) * PA + k0 + tig + 4];
            }
            #pragma unroll
            for (int nf = 0; nf < 4; nf++) {
                int nc = n_off + nf * 8 + g;
                b[nf][0] = Bs[(k0 + tig) * PB + nc];
                b[nf][1] = Bs[(k0 + tig + 4) * PB + nc];
            }
            #pragma unroll
            for (int mf = 0; mf < 2; mf++)
                #pragma unroll
                for (int nf = 0; nf < 4; nf++)
                    mma8(acc[mf][nf], a[mf], b[nf]);
        }
        __syncthreads();
    }

    #pragma unroll
    for (int mf = 0; mf < 2; mf++) {
        int r0 = m0 + m_off + mf * 16 + g;
        int r1 = r0 + 8;
        float b0 = (r0 < M) ? bias[r0] : 0.f;
        float b1 = (r1 < M) ? bias[r1] : 0.f;
        #pragma unroll
        for (int nf = 0; nf < 4; nf++) {
            int col = n0 + n_off + nf * 8 + 2 * tig;
            if (r0 < M) {
                float2 o = make_float2(acc[mf][nf][0] + b0, acc[mf][nf][1] + b0);
                *(float2*)&out[r0 * NPIX + col] = o;
            }
            if (r1 < M) {
                float2 o = make_float2(acc[mf][nf][2] + b1, acc[mf][nf][3] + b1);
                *(float2*)&out[r1 * NPIX + col] = o;
            }
        }
    }
}

// ---------------------------------------------------------------------------
// energy[m][n] = sum_{c<32} q[c][m]*k[c][n].  grid (32, 64), block 256.
// q kept in natural [c][m] layout (A frags index-swapped, no transpose store).
// ---------------------------------------------------------------------------
__global__ void energy_mma(const float* __restrict__ q,
                           const float* __restrict__ k,
                           float* __restrict__ e)
{
    __shared__ unsigned Qs[32 * PQ];
    __shared__ unsigned Ks[32 * PB];

    const int tid = threadIdx.x;
    const int lane = tid & 31, wid = tid >> 5;
    const int g = lane >> 2, tig = lane & 3;
    const int m_off = (wid >> 2) * 32, n_off = (wid & 3) * 32;
    const int m0 = blockIdx.y * 64, n0 = blockIdx.x * 128;

    #pragma unroll
    for (int r = 0; r < 2; r++) {
        int idx = tid + r * 256;
        int c = idx >> 4, m4 = (idx & 15) * 4;
        float4 v = *(const float4*)&q[c * NPIX + m0 + m4];
        unsigned* p = &Qs[c * PQ + m4];
        p[0] = f2tf32(v.x); p[1] = f2tf32(v.y); p[2] = f2tf32(v.z); p[3] = f2tf32(v.w);
    }
    #pragma unroll
    for (int r = 0; r < 4; r++) {
        int idx = tid + r * 256;
        int c = idx >> 5, c4 = (idx & 31) * 4;
        float4 v = *(const float4*)&k[c * NPIX + n0 + c4];
        unsigned* p = &Ks[c * PB + c4];
        p[0] = f2tf32(v.x); p[1] = f2tf32(v.y); p[2] = f2tf32(v.z); p[3] = f2tf32(v.w);
    }
    __syncthreads();

    float acc[2][4][4] = {};
    #pragma unroll
    for (int ks = 0; ks < 4; ks++) {
        const int k0 = ks * 8;
        unsigned a[2][4], b[4][2];
        #pragma unroll
        for (int mf = 0; mf < 2; mf++) {
            int mr = m_off + mf * 16 + g;
            a[mf][0] = Qs[(k0 + tig) * PQ + mr];
            a[mf][1] = Qs[(k0 + tig) * PQ + mr + 8];
            a[mf][2] = Qs[(k0 + tig + 4) * PQ + mr];
            a[mf][3] = Qs[(k0 + tig + 4) * PQ + mr + 8];
        }
        #pragma unroll
        for (int nf = 0; nf < 4; nf++) {
            int nc = n_off + nf * 8 + g;
            b[nf][0] = Ks[(k0 + tig) * PB + nc];
            b[nf][1] = Ks[(k0 + tig + 4) * PB + nc];
        }
        #pragma unroll
        for (int mf = 0; mf < 2; mf++)
            #pragma unroll
            for (int nf = 0; nf < 4; nf++)
                mma8(acc[mf][nf], a[mf], b[nf]);
    }

    #pragma unroll
    for (int mf = 0; mf < 2; mf++) {
        int r0 = m0 + m_off + mf * 16 + g;
        int r1 = r0 + 8;
        #pragma unroll
        for (int nf = 0; nf < 4; nf++) {
            int col = n0 + n_off + nf * 8 + 2 * tig;
            *(float2*)&e[(size_t)r0 * NPIX + col] = make_float2(acc[mf][nf][0], acc[mf][nf][1]);
            *(float2*)&e[(size_t)r1 * NPIX + col] = make_float2(acc[mf][nf][2], acc[mf][nf][3]);
        }
    }
}

// ---------------------------------------------------------------------------
// In-place row softmax over 4096 columns. grid 4096, block 256.
// ---------------------------------------------------------------------------
__global__ void softmax_kernel(float* __restrict__ e)
{
    __shared__ float red[8];
    float4* p = (float4*)(e + (size_t)blockIdx.x * NPIX);
    const int tid = threadIdx.x;
    float4 v[4];
    float mx = -1e30f;
    #pragma unroll
    for (int r = 0; r < 4; r++) {
        v[r] = p[tid + r * 256];
        mx = fmaxf(mx, fmaxf(fmaxf(v[r].x, v[r].y), fmaxf(v[r].z, v[r].w)));
    }
    #pragma unroll
    for (int o = 16; o > 0; o >>= 1)
        mx = fmaxf(mx, __shfl_xor_sync(0xffffffffu, mx, o));
    if ((tid & 31) == 0) red[tid >> 5] = mx;
    __syncthreads();
    mx = red[0];
    #pragma unroll
    for (int w = 1; w < 8; w++) mx = fmaxf(mx, red[w]);
    __syncthreads();

    float s = 0.f;
    #pragma unroll
    for (int r = 0; r < 4; r++) {
        v[r].x = __expf(v[r].x - mx); s += v[r].x;
        v[r].y = __expf(v[r].y - mx); s += v[r].y;
        v[r].z = __expf(v[r].z - mx); s += v[r].z;
        v[r].w = __expf(v[r].w - mx); s += v[r].w;
    }
    #pragma unroll
    for (int o = 16; o > 0; o >>= 1)
        s += __shfl_xor_sync(0xffffffffu, s, o);
    if ((tid & 31) == 0) red[tid >> 5] = s;
    __syncthreads();
    s = 0.f;
    #pragma unroll
    for (int w = 0; w < 8; w++) s += red[w];
    const float inv = 1.f / s;
    #pragma unroll
    for (int r = 0; r < 4; r++) {
        v[r].x *= inv; v[r].y *= inv; v[r].z *= inv; v[r].w *= inv;
        p[tid + r * 256] = v[r];
    }
}

// ---------------------------------------------------------------------------
// av: out[m][n] = gamma * sum_k v[m][k]*attn[n][k] + xq[m][n].
// attn tile kept row-natural [n][k]; B frags index-swapped. grid (32, 4).
// ---------------------------------------------------------------------------
__global__ void av_mma(const float* __restrict__ vmat,
                       const float* __restrict__ attn,
                       const float* __restrict__ xq,
                       const float* __restrict__ gamma,
                       float* __restrict__ out)
{
    __shared__ unsigned As[64 * PA];
    __shared__ unsigned Bt[128 * PT];

    const int tid = threadIdx.x;
    const int lane = tid & 31, wid = tid >> 5;
    const int g = lane >> 2, tig = lane & 3;
    const int m_off = (wid >> 2) * 32, n_off = (wid & 3) * 32;
    const int m0 = blockIdx.y * 64, n0 = blockIdx.x * 128;

    float acc[2][4][4] = {};

    for (int kt = 0; kt < NPIX; kt += 32) {
        #pragma unroll
        for (int r = 0; r < 2; r++) {
            int idx = tid + r * 256;
            int m = idx >> 3, c4 = (idx & 7) * 4;
            float4 v = *(const float4*)&vmat[(m0 + m) * NPIX + kt + c4];
            unsigned* a = &As[m * PA + c4];
            a[0] = f2tf32(v.x); a[1] = f2tf32(v.y); a[2] = f2tf32(v.z); a[3] = f2tf32(v.w);
        }
        #pragma unroll
        for (int r = 0; r < 4; r++) {
            int idx = tid + r * 256;
            int n = idx >> 3, c4 = (idx & 7) * 4;
            float4 v = *(const float4*)&attn[(size_t)(n0 + n) * NPIX + kt + c4];
            unsigned* bp = &Bt[n * PT + c4];
            bp[0] = f2tf32(v.x); bp[1] = f2tf32(v.y); bp[2] = f2tf32(v.z); bp[3] = f2tf32(v.w);
        }
        __syncthreads();
        #pragma unroll
        for (int ks = 0; ks < 4; ks++) {
            const int k0 = ks * 8;
            unsigned a[2][4], b[4][2];
            #pragma unroll
            for (int mf = 0; mf < 2; mf++) {
                int mr = m_off + mf * 16 + g;
                a[mf][0] = As[mr * PA + k0 + tig];
                a[mf][1] = As[(mr + 8) * PA + k0 + tig];
                a[mf][2] = As[mr * PA + k0 + tig + 4];
                a[mf][3] = As[(mr + 8) * PA + k0 + tig + 4];
            }
            #pragma unroll
            for (int nf = 0; nf < 4; nf++) {
                int nc = n_off + nf * 8 + g;
                b[nf][0] = Bt[nc * PT + k0 + tig];
                b[nf][1] = Bt[nc * PT + k0 + tig + 4];
            }
            #pragma unroll
            for (int mf = 0; mf < 2; mf++)
                #pragma unroll
                for (int nf = 0; nf < 4; nf++)
                    mma8(acc[mf][nf], a[mf], b[nf]);
        }
        __syncthreads();
    }

    const float gm = gamma[0];
    #pragma unroll
    for (int mf = 0; mf < 2; mf++) {
        int r0 = m0 + m_off + mf * 16 + g;
        int r1 = r0 + 8;
        #pragma unroll
        for (int nf = 0; nf < 4; nf++) {
            int col = n0 + n_off + nf * 8 + 2 * tig;
            float2 x0 = *(const float2*)&xq[r0 * NPIX + col];
            float2 x1 = *(const float2*)&xq[r1 * NPIX + col];
            float2 o0 = make_float2(gm * acc[mf][nf][0] + x0.x, gm * acc[mf][nf][1] + x0.y);
            float2 o1 = make_float2(gm * acc[mf][nf][2] + x1.x, gm * acc[mf][nf][3] + x1.y);
            *(float2*)&out[r0 * NPIX + col] = o0;
            *(float2*)&out[r1 * NPIX + col] = o1;
        }
    }
}

// ---------------------------------------------------------------------------
extern "C" void kernel_launch(void* const* d_in, const int* in_sizes, int n_in,
                              void* d_out, int out_size)
{
    const float* x1    = (const float*)d_in[0];
    const float* x2    = (const float*)d_in[1];
    const float* sx1_w = (const float*)d_in[2];
    const float* sy1_w = (const float*)d_in[3];
    const float* bn1x  = (const float*)d_in[4];
    const float* bn1y  = (const float*)d_in[5];
    const float* sx2_w = (const float*)d_in[6];
    const float* sy2_w = (const float*)d_in[7];
    const float* bn2x  = (const float*)d_in[8];
    const float* bn2y  = (const float*)d_in[9];
    const float* q1_w  = (const float*)d_in[10];
    const float* q1_b  = (const float*)d_in[11];
    const float* k1_w  = (const float*)d_in[12];
    const float* k1_b  = (const float*)d_in[13];
    const float* v1_w  = (const float*)d_in[14];
    const float* v1_b  = (const float*)d_in[15];
    const float* q2_w  = (const float*)d_in[16];
    const float* q2_b  = (const float*)d_in[17];
    const float* k2_w  = (const float*)d_in[18];
    const float* k2_b  = (const float*)d_in[19];
    const float* v2_w  = (const float*)d_in[20];
    const float* v2_b  = (const float*)d_in[21];
    const float* gamma1 = (const float*)d_in[22];
    const float* gamma2 = (const float*)d_in[23];
    float* out = (float*)d_out;

    float *xf1, *xf2, *qb, *kb, *vb, *attn, *wx1p, *wy1p, *wx2p, *wy2p;
    cudaGetSymbolAddress((void**)&xf1, g_xf1);
    cudaGetSymbolAddress((void**)&xf2, g_xf2);
    cudaGetSymbolAddress((void**)&qb,  g_qb);
    cudaGetSymbolAddress((void**)&kb,  g_kb);
    cudaGetSymbolAddress((void**)&vb,  g_vb);
    cudaGetSymbolAddress((void**)&attn, g_attn);
    cudaGetSymbolAddress((void**)&wx1p, g_wx1p);
    cudaGetSymbolAddress((void**)&wy1p, g_wy1p);
    cudaGetSymbolAddress((void**)&wx2p, g_wx2p);
    cudaGetSymbolAddress((void**)&wy2p, g_wy2p);

    dim3 blk(256);
    const int PACK_BLOCKS = CC * KW / 256;   // 2304

    pack_w<<<PACK_BLOCKS, blk>>>(sx1_w, wx1p);
    pack_w<<<PACK_BLOCKS, blk>>>(sy1_w, wy1p);
    pack_w<<<PACK_BLOCKS, blk>>>(sx2_w, wx2p);
    pack_w<<<PACK_BLOCKS, blk>>>(sy2_w, wy2p);

    sobel_mma<<<dim3(32, 4), blk>>>(x1, wx1p, wy1p, bn1x, bn1y, xf1);
    sobel_mma<<<dim3(32, 4), blk>>>(x2, wx2p, wy2p, bn2x, bn2y, xf2);

    // ---- attention 1: q from x1, k/v from xf2 -> out1 ----
    proj_mma<<<dim3(32, 1), blk>>>(q1_w, x1,  q1_b, qb, CQ);
    proj_mma<<<dim3(32, 1), blk>>>(k1_w, xf2, k1_b, kb, CQ);
    proj_mma<<<dim3(32, 4), blk>>>(v1_w, xf2, v1_b, vb, CC);
    energy_mma<<<dim3(32, 64), blk>>>(qb, kb, attn);
    softmax_kernel<<<NPIX, 256>>>(attn);
    av_mma<<<dim3(32, 4), blk>>>(vb, attn, x1, gamma1, out);

    // ---- attention 2: q from x2, k/v from xf1 -> out2 ----
    proj_mma<<<dim3(32, 1), blk>>>(q2_w, x2,  q2_b, qb, CQ);
    proj_mma<<<dim3(32, 1), blk>>>(k2_w, xf1, k2_b, kb, CQ);
    proj_mma<<<dim3(32, 4), blk>>>(v2_w, xf1, v2_b, vb, CC);
    energy_mma<<<dim3(32, 64), blk>>>(qb, kb, attn);
    softmax_kernel<<<NPIX, 256>>>(attn);
    av_mma<<<dim3(32, 4), blk>>>(vb, attn, x2, gamma2, out + CC * NPIX);
}

// round 4
// speedup vs baseline: 3.5353x; 1.8668x over previous
#include <cuda_runtime.h>
#include <math.h>

#define CC   256
#define CQ   32
#define NPIX 4096
#define EPSB 1e-5f
#define KW   2304          // 9*256 conv K

// smem row pads (u32 elems) chosen for conflict-free fragment LDS
#define PA 36              // A tiles [m][k]
#define PB 136             // B tiles [k][n]
#define PT 36              // B-transposed tiles [n][k]
#define PQ 68              // q tile [c][m]

// ---------------- scratch ----------------
__device__ float g_xf1[CC * NPIX];
__device__ float g_xf2[CC * NPIX];
__device__ float g_qb1[CQ * NPIX];
__device__ float g_kb1[CQ * NPIX];
__device__ float g_vb1[CC * NPIX];
__device__ float g_qb2[CQ * NPIX];
__device__ float g_kb2[CQ * NPIX];
__device__ float g_vb2[CC * NPIX];
__device__ float g_attn1[(size_t)NPIX * NPIX];
__device__ float g_attn2[(size_t)NPIX * NPIX];
__device__ float g_wx1p[CC * KW];
__device__ float g_wy1p[CC * KW];
__device__ float g_wx2p[CC * KW];
__device__ float g_wy2p[CC * KW];

// ---------------- tf32 mma helpers ----------------
__device__ __forceinline__ unsigned f2tf32(float x) {
    unsigned r; asm("cvt.rna.tf32.f32 %0, %1;" : "=r"(r) : "f"(x)); return r;
}
__device__ __forceinline__ void mma8(float* c, const unsigned* a, const unsigned* b) {
    asm volatile(
        "mma.sync.aligned.m16n8k8.row.col.f32.tf32.tf32.f32 "
        "{%0,%1,%2,%3}, {%4,%5,%6,%7}, {%8,%9}, {%0,%1,%2,%3};"
        : "+f"(c[0]), "+f"(c[1]), "+f"(c[2]), "+f"(c[3])
        : "r"(a[0]), "r"(a[1]), "r"(a[2]), "r"(a[3]), "r"(b[0]), "r"(b[1]));
}

// ---------------------------------------------------------------------------
// pack all 4 conv-weight tensors: w[m][ci][tap] -> wp[m][tap*256+ci]
// grid (2304, 4), block 256.
// ---------------------------------------------------------------------------
__global__ void pack_all(const float* __restrict__ s0, const float* __restrict__ s1,
                         const float* __restrict__ s2, const float* __restrict__ s3,
                         float* __restrict__ d0, float* __restrict__ d1,
                         float* __restrict__ d2, float* __restrict__ d3)
{
    const int y = blockIdx.y;
    const float* s = (y == 0) ? s0 : (y == 1) ? s1 : (y == 2) ? s2 : s3;
    float* d = (y == 0) ? d0 : (y == 1) ? d1 : (y == 2) ? d2 : d3;
    int t = blockIdx.x * 256 + threadIdx.x;
    int m = t / KW, r = t % KW;
    d[t] = s[m * KW + (r & 255) * 9 + (r >> 8)];
}

// ---------------------------------------------------------------------------
// Sobel (batched z=2): dual conv3x3 GEMM + BN + magnitude, double-buffered.
// grid (32, 4, 2), block 256, dynamic smem.
// ---------------------------------------------------------------------------
__global__ void sobel_mma(const float* __restrict__ x1a, const float* __restrict__ wx1,
                          const float* __restrict__ wy1, const float* __restrict__ bn1x,
                          const float* __restrict__ bn1y, float* __restrict__ o1,
                          const float* __restrict__ x2a, const float* __restrict__ wx2,
                          const float* __restrict__ wy2, const float* __restrict__ bn2x,
                          const float* __restrict__ bn2y, float* __restrict__ o2)
{
    extern __shared__ unsigned sh[];
    unsigned* AxB = sh;                       // 2 * 64*PA
    unsigned* AyB = sh + 2 * 64 * PA;
    unsigned* BsB = sh + 4 * 64 * PA;         // 2 * 32*PB

    const int z = blockIdx.z;
    const float* x   = z ? x2a : x1a;
    const float* wxp = z ? wx2 : wx1;
    const float* wyp = z ? wy2 : wy1;
    const float* bnx = z ? bn2x : bn1x;
    const float* bny = z ? bn2y : bn1y;
    float* out = z ? o2 : o1;

    const int tid = threadIdx.x;
    const int lane = tid & 31, wid = tid >> 5;
    const int g = lane >> 2, tig = lane & 3;
    const int m_off = (wid >> 2) * 32, n_off = (wid & 3) * 32;
    const int m0 = blockIdx.y * 64, n0 = blockIdx.x * 128;

    float accx[2][4][4] = {};
    float accy[2][4][4] = {};

    float4 rAx[2], rAy[2];
    float rB[4][4];

    // index precompute for cooperative loads
    const int amr = tid >> 3, ac4 = (tid & 7) * 4;          // A: row, col4 (stride 32 rows per r)
    const int bkl = tid >> 5, bc4 = (tid & 31) * 4;         // B: k-lane, col4 (stride 8 k per r)

    #define S_LOAD_A(kt) { \
        rAx[0] = *(const float4*)&wxp[(m0 + amr) * KW + (kt) + ac4]; \
        rAy[0] = *(const float4*)&wyp[(m0 + amr) * KW + (kt) + ac4]; \
        rAx[1] = *(const float4*)&wxp[(m0 + amr + 32) * KW + (kt) + ac4]; \
        rAy[1] = *(const float4*)&wyp[(m0 + amr + 32) * KW + (kt) + ac4]; }

    #define S_LOAD_B(kt) { \
        const int tap = (kt) >> 8; \
        const int dy = tap / 3 - 1, dx = tap % 3 - 1; \
        const int cibase = (kt) & 255; \
        _Pragma("unroll") \
        for (int r = 0; r < 4; r++) { \
            int ci = cibase + bkl + r * 8; \
            _Pragma("unroll") \
            for (int j = 0; j < 4; j++) { \
                int pix = n0 + bc4 + j; \
                int yy = (pix >> 6) + dy; \
                int xx = (pix & 63) + dx; \
                float f = 0.f; \
                if (yy >= 0 && yy < 64 && xx >= 0 && xx < 64) \
                    f = x[ci * NPIX + yy * 64 + xx]; \
                rB[r][j] = f; \
            } \
        } }

    #define S_STORE(buf) { \
        unsigned* Ax = AxB + (buf) * 64 * PA; \
        unsigned* Ay = AyB + (buf) * 64 * PA; \
        unsigned* Bs = BsB + (buf) * 32 * PB; \
        unsigned* p0 = &Ax[amr * PA + ac4]; \
        p0[0]=f2tf32(rAx[0].x); p0[1]=f2tf32(rAx[0].y); p0[2]=f2tf32(rAx[0].z); p0[3]=f2tf32(rAx[0].w); \
        unsigned* p1 = &Ax[(amr + 32) * PA + ac4]; \
        p1[0]=f2tf32(rAx[1].x); p1[1]=f2tf32(rAx[1].y); p1[2]=f2tf32(rAx[1].z); p1[3]=f2tf32(rAx[1].w); \
        unsigned* p2 = &Ay[amr * PA + ac4]; \
        p2[0]=f2tf32(rAy[0].x); p2[1]=f2tf32(rAy[0].y); p2[2]=f2tf32(rAy[0].z); p2[3]=f2tf32(rAy[0].w); \
        unsigned* p3 = &Ay[(amr + 32) * PA + ac4]; \
        p3[0]=f2tf32(rAy[1].x); p3[1]=f2tf32(rAy[1].y); p3[2]=f2tf32(rAy[1].z); p3[3]=f2tf32(rAy[1].w); \
        _Pragma("unroll") \
        for (int r = 0; r < 4; r++) { \
            unsigned* bp = &Bs[(bkl + r * 8) * PB + bc4]; \
            bp[0]=f2tf32(rB[r][0]); bp[1]=f2tf32(rB[r][1]); bp[2]=f2tf32(rB[r][2]); bp[3]=f2tf32(rB[r][3]); \
        } }

    S_LOAD_A(0); S_LOAD_B(0);
    S_STORE(0);
    __syncthreads();

    int buf = 0;
    for (int c = 0; c < KW / 32; c++) {
        const bool more = (c + 1 < KW / 32);
        if (more) { const int ktn = (c + 1) * 32; S_LOAD_A(ktn); S_LOAD_B(ktn); }

        const unsigned* Ax = AxB + buf * 64 * PA;
        const unsigned* Ay = AyB + buf * 64 * PA;
        const unsigned* Bs = BsB + buf * 32 * PB;
        #pragma unroll
        for (int ks = 0; ks < 4; ks++) {
            const int k0 = ks * 8;
            unsigned ax[2][4], ay[2][4], b[4][2];
            #pragma unroll
            for (int mf = 0; mf < 2; mf++) {
                int mr = m_off + mf * 16 + g;
                ax[mf][0] = Ax[mr * PA + k0 + tig];
                ax[mf][1] = Ax[(mr + 8) * PA + k0 + tig];
                ax[mf][2] = Ax[mr * PA + k0 + tig + 4];
                ax[mf][3] = Ax[(mr + 8) * PA + k0 + tig + 4];
                ay[mf][0] = Ay[mr * PA + k0 + tig];
                ay[mf][1] = Ay[(mr + 8) * PA + k0 + tig];
                ay[mf][2] = Ay[mr * PA + k0 + tig + 4];
                ay[mf][3] = Ay[(mr + 8) * PA + k0 + tig + 4];
            }
            #pragma unroll
            for (int nf = 0; nf < 4; nf++) {
                int nc = n_off + nf * 8 + g;
                b[nf][0] = Bs[(k0 + tig) * PB + nc];
                b[nf][1] = Bs[(k0 + tig + 4) * PB + nc];
            }
            #pragma unroll
            for (int mf = 0; mf < 2; mf++)
                #pragma unroll
                for (int nf = 0; nf < 4; nf++) {
                    mma8(accx[mf][nf], ax[mf], b[nf]);
                    mma8(accy[mf][nf], ay[mf], b[nf]);
                }
        }
        if (more) S_STORE(buf ^ 1);
        __syncthreads();
        buf ^= 1;
    }

    #pragma unroll
    for (int mf = 0; mf < 2; mf++) {
        int r0 = m0 + m_off + mf * 16 + g;
        int r1 = r0 + 8;
        float ivx0 = bnx[r0] * rsqrtf(bnx[768 + r0] + EPSB);
        float ivx1 = bnx[r1] * rsqrtf(bnx[768 + r1] + EPSB);
        float bx0 = bnx[256 + r0], bx1 = bnx[256 + r1];
        float mx0 = bnx[512 + r0], mx1 = bnx[512 + r1];
        float ivy0 = bny[r0] * rsqrtf(bny[768 + r0] + EPSB);
        float ivy1 = bny[r1] * rsqrtf(bny[768 + r1] + EPSB);
        float by0 = bny[256 + r0], by1 = bny[256 + r1];
        float my0 = bny[512 + r0], my1 = bny[512 + r1];
        #pragma unroll
        for (int nf = 0; nf < 4; nf++) {
            int col = n0 + n_off + nf * 8 + 2 * tig;
            float gx, gy;
            float2 o0, o1;
            gx = (accx[mf][nf][0] - mx0) * ivx0 + bx0;
            gy = (accy[mf][nf][0] - my0) * ivy0 + by0;
            o0.x = sqrtf(gx * gx + gy * gy);
            gx = (accx[mf][nf][1] - mx0) * ivx0 + bx0;
            gy = (accy[mf][nf][1] - my0) * ivy0 + by0;
            o0.y = sqrtf(gx * gx + gy * gy);
            gx = (accx[mf][nf][2] - mx1) * ivx1 + bx1;
            gy = (accy[mf][nf][2] - my1) * ivy1 + by1;
            o1.x = sqrtf(gx * gx + gy * gy);
            gx = (accx[mf][nf][3] - mx1) * ivx1 + bx1;
            gy = (accy[mf][nf][3] - my1) * ivy1 + by1;
            o1.y = sqrtf(gx * gx + gy * gy);
            *(float2*)&out[r0 * NPIX + col] = o0;
            *(float2*)&out[r1 * NPIX + col] = o1;
        }
    }
}

// ---------------------------------------------------------------------------
// proj (batched): out[M][4096] = W[M][256] * B + bias. z selects arg set.
// grid (32, ceil(M/64), nz), block 256, dynamic smem, double-buffered.
// ---------------------------------------------------------------------------
struct ProjArgs {
    const float* A[4];
    const float* B[4];
    const float* bias[4];
    float* out[4];
    int M;
};

__global__ void __launch_bounds__(256, 2) proj_mma(ProjArgs args)
{
    extern __shared__ unsigned sh[];
    unsigned* AsB = sh;                       // 2 * 64*PA
    unsigned* BsB = sh + 2 * 64 * PA;         // 2 * 32*PB

    const int z = blockIdx.z;
    const float* A = args.A[z];
    const float* B = args.B[z];
    const float* bias = args.bias[z];
    float* out = args.out[z];
    const int M = args.M;

    const int tid = threadIdx.x;
    const int lane = tid & 31, wid = tid >> 5;
    const int g = lane >> 2, tig = lane & 3;
    const int m_off = (wid >> 2) * 32, n_off = (wid & 3) * 32;
    const int m0 = blockIdx.y * 64, n0 = blockIdx.x * 128;

    float acc[2][4][4] = {};
    float4 rA[2], rB[4];

    const int amr = tid >> 3, ac4 = (tid & 7) * 4;
    const int bkl = tid >> 5, bc4 = (tid & 31) * 4;

    #define P_LOAD(kt) { \
        rA[0] = (m0 + amr < M) ? *(const float4*)&A[(m0 + amr) * 256 + (kt) + ac4] \
                               : make_float4(0.f, 0.f, 0.f, 0.f); \
        rA[1] = (m0 + amr + 32 < M) ? *(const float4*)&A[(m0 + amr + 32) * 256 + (kt) + ac4] \
                                    : make_float4(0.f, 0.f, 0.f, 0.f); \
        _Pragma("unroll") \
        for (int r = 0; r < 4; r++) \
            rB[r] = *(const float4*)&B[((kt) + bkl + r * 8) * NPIX + n0 + bc4]; }

    #define P_STORE(buf) { \
        unsigned* As = AsB + (buf) * 64 * PA; \
        unsigned* Bs = BsB + (buf) * 32 * PB; \
        unsigned* p0 = &As[amr * PA + ac4]; \
        p0[0]=f2tf32(rA[0].x); p0[1]=f2tf32(rA[0].y); p0[2]=f2tf32(rA[0].z); p0[3]=f2tf32(rA[0].w); \
        unsigned* p1 = &As[(amr + 32) * PA + ac4]; \
        p1[0]=f2tf32(rA[1].x); p1[1]=f2tf32(rA[1].y); p1[2]=f2tf32(rA[1].z); p1[3]=f2tf32(rA[1].w); \
        _Pragma("unroll") \
        for (int r = 0; r < 4; r++) { \
            unsigned* bp = &Bs[(bkl + r * 8) * PB + bc4]; \
            bp[0]=f2tf32(rB[r].x); bp[1]=f2tf32(rB[r].y); bp[2]=f2tf32(rB[r].z); bp[3]=f2tf32(rB[r].w); \
        } }

    P_LOAD(0);
    P_STORE(0);
    __syncthreads();

    int buf = 0;
    for (int c = 0; c < 8; c++) {
        const bool more = (c + 1 < 8);
        if (more) { const int ktn = (c + 1) * 32; P_LOAD(ktn); }

        const unsigned* As = AsB + buf * 64 * PA;
        const unsigned* Bs = BsB + buf * 32 * PB;
        #pragma unroll
        for (int ks = 0; ks < 4; ks++) {
            const int k0 = ks * 8;
            unsigned a[2][4], b[4][2];
            #pragma unroll
            for (int mf = 0; mf < 2; mf++) {
                int mr = m_off + mf * 16 + g;
                a[mf][0] = As[mr * PA + k0 + tig];
                a[mf][1] = As[(mr + 8) * PA + k0 + tig];
                a[mf][2] = As[mr * PA + k0 + tig + 4];
                a[mf][3] = As[(mr + 8) * PA + k0 + tig + 4];
            }
            #pragma unroll
            for (int nf = 0; nf < 4; nf++) {
                int nc = n_off + nf * 8 + g;
                b[nf][0] = Bs[(k0 + tig) * PB + nc];
                b[nf][1] = Bs[(k0 + tig + 4) * PB + nc];
            }
            #pragma unroll
            for (int mf = 0; mf < 2; mf++)
                #pragma unroll
                for (int nf = 0; nf < 4; nf++)
                    mma8(acc[mf][nf], a[mf], b[nf]);
        }
        if (more) P_STORE(buf ^ 1);
        __syncthreads();
        buf ^= 1;
    }

    #pragma unroll
    for (int mf = 0; mf < 2; mf++) {
        int r0 = m0 + m_off + mf * 16 + g;
        int r1 = r0 + 8;
        float b0 = (r0 < M) ? bias[r0] : 0.f;
        float b1 = (r1 < M) ? bias[r1] : 0.f;
        #pragma unroll
        for (int nf = 0; nf < 4; nf++) {
            int col = n0 + n_off + nf * 8 + 2 * tig;
            if (r0 < M)
                *(float2*)&out[r0 * NPIX + col] =
                    make_float2(acc[mf][nf][0] + b0, acc[mf][nf][1] + b0);
            if (r1 < M)
                *(float2*)&out[r1 * NPIX + col] =
                    make_float2(acc[mf][nf][2] + b1, acc[mf][nf][3] + b1);
        }
    }
}

// ---------------------------------------------------------------------------
// energy (batched z=2). grid (32, 64, 2), block 256.
// ---------------------------------------------------------------------------
__global__ void energy_mma(const float* __restrict__ q1, const float* __restrict__ k1,
                           float* __restrict__ e1,
                           const float* __restrict__ q2, const float* __restrict__ k2,
                           float* __restrict__ e2)
{
    __shared__ unsigned Qs[32 * PQ];
    __shared__ unsigned Ks[32 * PB];

    const int z = blockIdx.z;
    const float* q = z ? q2 : q1;
    const float* k = z ? k2 : k1;
    float* e = z ? e2 : e1;

    const int tid = threadIdx.x;
    const int lane = tid & 31, wid = tid >> 5;
    const int g = lane >> 2, tig = lane & 3;
    const int m_off = (wid >> 2) * 32, n_off = (wid & 3) * 32;
    const int m0 = blockIdx.y * 64, n0 = blockIdx.x * 128;

    #pragma unroll
    for (int r = 0; r < 2; r++) {
        int idx = tid + r * 256;
        int c = idx >> 4, m4 = (idx & 15) * 4;
        float4 v = *(const float4*)&q[c * NPIX + m0 + m4];
        unsigned* p = &Qs[c * PQ + m4];
        p[0] = f2tf32(v.x); p[1] = f2tf32(v.y); p[2] = f2tf32(v.z); p[3] = f2tf32(v.w);
    }
    #pragma unroll
    for (int r = 0; r < 4; r++) {
        int idx = tid + r * 256;
        int c = idx >> 5, c4 = (idx & 31) * 4;
        float4 v = *(const float4*)&k[c * NPIX + n0 + c4];
        unsigned* p = &Ks[c * PB + c4];
        p[0] = f2tf32(v.x); p[1] = f2tf32(v.y); p[2] = f2tf32(v.z); p[3] = f2tf32(v.w);
    }
    __syncthreads();

    float acc[2][4][4] = {};
    #pragma unroll
    for (int ks = 0; ks < 4; ks++) {
        const int k0 = ks * 8;
        unsigned a[2][4], b[4][2];
        #pragma unroll
        for (int mf = 0; mf < 2; mf++) {
            int mr = m_off + mf * 16 + g;
            a[mf][0] = Qs[(k0 + tig) * PQ + mr];
            a[mf][1] = Qs[(k0 + tig) * PQ + mr + 8];
            a[mf][2] = Qs[(k0 + tig + 4) * PQ + mr];
            a[mf][3] = Qs[(k0 + tig + 4) * PQ + mr + 8];
        }
        #pragma unroll
        for (int nf = 0; nf < 4; nf++) {
            int nc = n_off + nf * 8 + g;
            b[nf][0] = Ks[(k0 + tig) * PB + nc];
            b[nf][1] = Ks[(k0 + tig + 4) * PB + nc];
        }
        #pragma unroll
        for (int mf = 0; mf < 2; mf++)
            #pragma unroll
            for (int nf = 0; nf < 4; nf++)
                mma8(acc[mf][nf], a[mf], b[nf]);
    }

    #pragma unroll
    for (int mf = 0; mf < 2; mf++) {
        int r0 = m0 + m_off + mf * 16 + g;
        int r1 = r0 + 8;
        #pragma unroll
        for (int nf = 0; nf < 4; nf++) {
            int col = n0 + n_off + nf * 8 + 2 * tig;
            *(float2*)&e[(size_t)r0 * NPIX + col] = make_float2(acc[mf][nf][0], acc[mf][nf][1]);
            *(float2*)&e[(size_t)r1 * NPIX + col] = make_float2(acc[mf][nf][2], acc[mf][nf][3]);
        }
    }
}

// ---------------------------------------------------------------------------
// softmax (batched z=2): in-place row softmax. grid (4096, 2), block 256.
// ---------------------------------------------------------------------------
__global__ void softmax_kernel(float* __restrict__ e1, float* __restrict__ e2)
{
    __shared__ float red[8];
    float* e = blockIdx.y ? e2 : e1;
    float4* p = (float4*)(e + (size_t)blockIdx.x * NPIX);
    const int tid = threadIdx.x;
    float4 v[4];
    float mx = -1e30f;
    #pragma unroll
    for (int r = 0; r < 4; r++) {
        v[r] = p[tid + r * 256];
        mx = fmaxf(mx, fmaxf(fmaxf(v[r].x, v[r].y), fmaxf(v[r].z, v[r].w)));
    }
    #pragma unroll
    for (int o = 16; o > 0; o >>= 1)
        mx = fmaxf(mx, __shfl_xor_sync(0xffffffffu, mx, o));
    if ((tid & 31) == 0) red[tid >> 5] = mx;
    __syncthreads();
    mx = red[0];
    #pragma unroll
    for (int w = 1; w < 8; w++) mx = fmaxf(mx, red[w]);
    __syncthreads();

    float s = 0.f;
    #pragma unroll
    for (int r = 0; r < 4; r++) {
        v[r].x = __expf(v[r].x - mx); s += v[r].x;
        v[r].y = __expf(v[r].y - mx); s += v[r].y;
        v[r].z = __expf(v[r].z - mx); s += v[r].z;
        v[r].w = __expf(v[r].w - mx); s += v[r].w;
    }
    #pragma unroll
    for (int o = 16; o > 0; o >>= 1)
        s += __shfl_xor_sync(0xffffffffu, s, o);
    if ((tid & 31) == 0) red[tid >> 5] = s;
    __syncthreads();
    s = 0.f;
    #pragma unroll
    for (int w = 0; w < 8; w++) s += red[w];
    const float inv = 1.f / s;
    #pragma unroll
    for (int r = 0; r < 4; r++) {
        v[r].x *= inv; v[r].y *= inv; v[r].z *= inv; v[r].w *= inv;
        p[tid + r * 256] = v[r];
    }
}

// ---------------------------------------------------------------------------
// av (batched z=2): out = gamma * V @ attn^T + xq. grid (32, 4, 2), block 256.
// dynamic smem, double-buffered.
// ---------------------------------------------------------------------------
__global__ void __launch_bounds__(256, 2) av_mma(
    const float* __restrict__ v1, const float* __restrict__ at1,
    const float* __restrict__ xq1, const float* __restrict__ gm1,
    const float* __restrict__ v2, const float* __restrict__ at2,
    const float* __restrict__ xq2, const float* __restrict__ gm2,
    float* __restrict__ outbase)
{
    extern __shared__ unsigned sh[];
    unsigned* AsB = sh;                       // 2 * 64*PA
    unsigned* BtB = sh + 2 * 64 * PA;         // 2 * 128*PT

    const int z = blockIdx.z;
    const float* vmat = z ? v2 : v1;
    const float* attn = z ? at2 : at1;
    const float* xq   = z ? xq2 : xq1;
    const float* gmp  = z ? gm2 : gm1;
    float* out = outbase + (size_t)z * CC * NPIX;

    const int tid = threadIdx.x;
    const int lane = tid & 31, wid = tid >> 5;
    const int g = lane >> 2, tig = lane & 3;
    const int m_off = (wid >> 2) * 32, n_off = (wid & 3) * 32;
    const int m0 = blockIdx.y * 64, n0 = blockIdx.x * 128;

    float acc[2][4][4] = {};
    float4 rA[2], rB[4];

    const int amr = tid >> 3, ac4 = (tid & 7) * 4;
    const int bnr = tid >> 3, bc4b = (tid & 7) * 4;

    #define V_LOAD(kt) { \
        rA[0] = *(const float4*)&vmat[(m0 + amr) * NPIX + (kt) + ac4]; \
        rA[1] = *(const float4*)&vmat[(m0 + amr + 32) * NPIX + (kt) + ac4]; \
        _Pragma("unroll") \
        for (int r = 0; r < 4; r++) \
            rB[r] = *(const float4*)&attn[(size_t)(n0 + bnr + r * 32) * NPIX + (kt) + bc4b]; }

    #define V_STORE(buf) { \
        unsigned* As = AsB + (buf) * 64 * PA; \
        unsigned* Bt = BtB + (buf) * 128 * PT; \
        unsigned* p0 = &As[amr * PA + ac4]; \
        p0[0]=f2tf32(rA[0].x); p0[1]=f2tf32(rA[0].y); p0[2]=f2tf32(rA[0].z); p0[3]=f2tf32(rA[0].w); \
        unsigned* p1 = &As[(amr + 32) * PA + ac4]; \
        p1[0]=f2tf32(rA[1].x); p1[1]=f2tf32(rA[1].y); p1[2]=f2tf32(rA[1].z); p1[3]=f2tf32(rA[1].w); \
        _Pragma("unroll") \
        for (int r = 0; r < 4; r++) { \
            unsigned* bp = &Bt[(bnr + r * 32) * PT + bc4b]; \
            bp[0]=f2tf32(rB[r].x); bp[1]=f2tf32(rB[r].y); bp[2]=f2tf32(rB[r].z); bp[3]=f2tf32(rB[r].w); \
        } }

    V_LOAD(0);
    V_STORE(0);
    __syncthreads();

    int buf = 0;
    for (int c = 0; c < NPIX / 32; c++) {
        const bool more = (c + 1 < NPIX / 32);
        if (more) { const int ktn = (c + 1) * 32; V_LOAD(ktn); }

        const unsigned* As = AsB + buf * 64 * PA;
        const unsigned* Bt = BtB + buf * 128 * PT;
        #pragma unroll
        for (int ks = 0; ks < 4; ks++) {
            const int k0 = ks * 8;
            unsigned a[2][4], b[4][2];
            #pragma unroll
            for (int mf = 0; mf < 2; mf++) {
                int mr = m_off + mf * 16 + g;
                a[mf][0] = As[mr * PA + k0 + tig];
                a[mf][1] = As[(mr + 8) * PA + k0 + tig];
                a[mf][2] = As[mr * PA + k0 + tig + 4];
                a[mf][3] = As[(mr + 8) * PA + k0 + tig + 4];
            }
            #pragma unroll
            for (int nf = 0; nf < 4; nf++) {
                int nc = n_off + nf * 8 + g;
                b[nf][0] = Bt[nc * PT + k0 + tig];
                b[nf][1] = Bt[nc * PT + k0 + tig + 4];
            }
            #pragma unroll
            for (int mf = 0; mf < 2; mf++)
                #pragma unroll
                for (int nf = 0; nf < 4; nf++)
                    mma8(acc[mf][nf], a[mf], b[nf]);
        }
        if (more) V_STORE(buf ^ 1);
        __syncthreads();
        buf ^= 1;
    }

    const float gm = gmp[0];
    #pragma unroll
    for (int mf = 0; mf < 2; mf++) {
        int r0 = m0 + m_off + mf * 16 + g;
        int r1 = r0 + 8;
        #pragma unroll
        for (int nf = 0; nf < 4; nf++) {
            int col = n0 + n_off + nf * 8 + 2 * tig;
            float2 x0 = *(const float2*)&xq[r0 * NPIX + col];
            float2 x1 = *(const float2*)&xq[r1 * NPIX + col];
            *(float2*)&out[r0 * NPIX + col] =
                make_float2(gm * acc[mf][nf][0] + x0.x, gm * acc[mf][nf][1] + x0.y);
            *(float2*)&out[r1 * NPIX + col] =
                make_float2(gm * acc[mf][nf][2] + x1.x, gm * acc[mf][nf][3] + x1.y);
        }
    }
}

// ---------------------------------------------------------------------------
extern "C" void kernel_launch(void* const* d_in, const int* in_sizes, int n_in,
                              void* d_out, int out_size)
{
    const float* x1    = (const float*)d_in[0];
    const float* x2    = (const float*)d_in[1];
    const float* sx1_w = (const float*)d_in[2];
    const float* sy1_w = (const float*)d_in[3];
    const float* bn1x  = (const float*)d_in[4];
    const float* bn1y  = (const float*)d_in[5];
    const float* sx2_w = (const float*)d_in[6];
    const float* sy2_w = (const float*)d_in[7];
    const float* bn2x  = (const float*)d_in[8];
    const float* bn2y  = (const float*)d_in[9];
    const float* q1_w  = (const float*)d_in[10];
    const float* q1_b  = (const float*)d_in[11];
    const float* k1_w  = (const float*)d_in[12];
    const float* k1_b  = (const float*)d_in[13];
    const float* v1_w  = (const float*)d_in[14];
    const float* v1_b  = (const float*)d_in[15];
    const float* q2_w  = (const float*)d_in[16];
    const float* q2_b  = (const float*)d_in[17];
    const float* k2_w  = (const float*)d_in[18];
    const float* k2_b  = (const float*)d_in[19];
    const float* v2_w  = (const float*)d_in[20];
    const float* v2_b  = (const float*)d_in[21];
    const float* gamma1 = (const float*)d_in[22];
    const float* gamma2 = (const float*)d_in[23];
    float* out = (float*)d_out;

    float *xf1, *xf2, *qb1, *kb1, *vb1, *qb2, *kb2, *vb2, *attn1, *attn2;
    float *wx1p, *wy1p, *wx2p, *wy2p;
    cudaGetSymbolAddress((void**)&xf1, g_xf1);
    cudaGetSymbolAddress((void**)&xf2, g_xf2);
    cudaGetSymbolAddress((void**)&qb1, g_qb1);
    cudaGetSymbolAddress((void**)&kb1, g_kb1);
    cudaGetSymbolAddress((void**)&vb1, g_vb1);
    cudaGetSymbolAddress((void**)&qb2, g_qb2);
    cudaGetSymbolAddress((void**)&kb2, g_kb2);
    cudaGetSymbolAddress((void**)&vb2, g_vb2);
    cudaGetSymbolAddress((void**)&attn1, g_attn1);
    cudaGetSymbolAddress((void**)&attn2, g_attn2);
    cudaGetSymbolAddress((void**)&wx1p, g_wx1p);
    cudaGetSymbolAddress((void**)&wy1p, g_wy1p);
    cudaGetSymbolAddress((void**)&wx2p, g_wx2p);
    cudaGetSymbolAddress((void**)&wy2p, g_wy2p);

    const int SOBEL_SMEM = (4 * 64 * PA + 2 * 32 * PB) * 4;   // 71680
    const int PROJ_SMEM  = (2 * 64 * PA + 2 * 32 * PB) * 4;   // 53248
    const int AV_SMEM    = (2 * 64 * PA + 2 * 128 * PT) * 4;  // 55296
    cudaFuncSetAttribute(sobel_mma, cudaFuncAttributeMaxDynamicSharedMemorySize, SOBEL_SMEM);
    cudaFuncSetAttribute(proj_mma,  cudaFuncAttributeMaxDynamicSharedMemorySize, PROJ_SMEM);
    cudaFuncSetAttribute(av_mma,    cudaFuncAttributeMaxDynamicSharedMemorySize, AV_SMEM);

    dim3 blk(256);

    pack_all<<<dim3(CC * KW / 256, 4), blk>>>(sx1_w, sy1_w, sx2_w, sy2_w,
                                              wx1p, wy1p, wx2p, wy2p);

    sobel_mma<<<dim3(32, 4, 2), blk, SOBEL_SMEM>>>(
        x1, wx1p, wy1p, bn1x, bn1y, xf1,
        x2, wx2p, wy2p, bn2x, bn2y, xf2);

    // q/k projections (4 batched, M=32)
    ProjArgs qk;
    qk.A[0] = q1_w;  qk.B[0] = x1;  qk.bias[0] = q1_b; qk.out[0] = qb1;
    qk.A[1] = k1_w;  qk.B[1] = xf2; qk.bias[1] = k1_b; qk.out[1] = kb1;
    qk.A[2] = q2_w;  qk.B[2] = x2;  qk.bias[2] = q2_b; qk.out[2] = qb2;
    qk.A[3] = k2_w;  qk.B[3] = xf1; qk.bias[3] = k2_b; qk.out[3] = kb2;
    qk.M = CQ;
    proj_mma<<<dim3(32, 1, 4), blk, PROJ_SMEM>>>(qk);

    // v projections (2 batched, M=256)
    ProjArgs vv;
    vv.A[0] = v1_w;  vv.B[0] = xf2; vv.bias[0] = v1_b; vv.out[0] = vb1;
    vv.A[1] = v2_w;  vv.B[1] = xf1; vv.bias[1] = v2_b; vv.out[1] = vb2;
    vv.A[2] = v1_w;  vv.B[2] = xf2; vv.bias[2] = v1_b; vv.out[2] = vb1;
    vv.A[3] = v1_w;  vv.B[3] = xf2; vv.bias[3] = v1_b; vv.out[3] = vb1;
    vv.M = CC;
    proj_mma<<<dim3(32, 4, 2), blk, PROJ_SMEM>>>(vv);

    energy_mma<<<dim3(32, 64, 2), blk>>>(qb1, kb1, attn1, qb2, kb2, attn2);
    softmax_kernel<<<dim3(NPIX, 2), blk>>>(attn1, attn2);
    av_mma<<<dim3(32, 4, 2), blk, AV_SMEM>>>(vb1, attn1, x1, gamma1,
                                             vb2, attn2, x2, gamma2, out);
}